// round 14
// baseline (speedup 1.0000x reference)
#include <cuda_runtime.h>
#include <cuda_bf16.h>
#include <cstdint>

#define N_NODES_MAX 50000
#define D_FEAT 128
#define H1 128
#define H2 64

// Scratch: per-node precomputed attention contributions (bias folded into A1).
__device__ float g_A1[N_NODES_MAX * H2];
__device__ float g_A2[N_NODES_MAX * H2];
__device__ int   g_edges_are_i64;   // 1 if edge buffer is int64, 0 if int32

// ---------------- smem layout ----------------
#define TM 128
#define SF 132           // padded row stride for F/H tile (floats); 132%32=4 -> conflict-free quads
#define NODE_SMEM_BYTES (TM * SF * 4)    // 67584 B -> 2-3 blocks/SM
#define NODE_THREADS 256

// 3xTF32 helpers -------------------------------------------------------------
// hi = tf32 truncation (exact mask), lo = exact fp32 remainder.
// hi*hi + hi*lo + lo*hi recovers ~fp32 precision (missing lo*lo ~ 2^-20).
__device__ __forceinline__ void split_tf32(float x, uint32_t& hi, uint32_t& lo) {
    uint32_t xb = __float_as_uint(x);
    hi = xb & 0xFFFFE000u;
    lo = __float_as_uint(x - __uint_as_float(hi));
}

__device__ __forceinline__ void mma_tf32(float* d, const uint32_t* a, const uint32_t* b) {
    asm volatile(
        "mma.sync.aligned.m16n8k8.row.col.f32.tf32.tf32.f32 "
        "{%0,%1,%2,%3}, {%4,%5,%6,%7}, {%8,%9}, {%0,%1,%2,%3};\n"
        : "+f"(d[0]), "+f"(d[1]), "+f"(d[2]), "+f"(d[3])
        : "r"(a[0]), "r"(a[1]), "r"(a[2]), "r"(a[3]), "r"(b[0]), "r"(b[1]));
}

// ---------------- Node precompute kernel ----------------
// gridDim.x = ceil(nNodes/128), gridDim.y = 2 (path 0 = nb/A1, path 1 = self/A2)
// 256 threads = 8 warps.
// Phase 1 (tensor, 3xTF32): H[128][128] = relu(F @ W + b); warp grid 2x4, tile 64x32.
//   A fragments from smem FH; B (=W^T) fragments DIRECTLY from gmem via __ldg (L1-hot).
// Phase 2 (FMA pipe, exact fp32): A[128][64] = H @ Wa (+b_att1); 8x4 micro-tile per thread,
//   Wa via __ldg. Runs on the fma pipe -> overlaps with other blocks' phase-1 tensor work.
extern "C" __global__ void __launch_bounds__(NODE_THREADS, 2)
node_precompute_kernel(const float* __restrict__ features,
                       const int*   __restrict__ edges_words,
                       const float* __restrict__ W_nb,
                       const float* __restrict__ b_nb,
                       const float* __restrict__ W_self,
                       const float* __restrict__ b_self,
                       const float* __restrict__ W_att1,
                       const float* __restrict__ b_att1,
                       int nNodes)
{
    extern __shared__ float FH[];    // [TM][SF] : F, later H

    const int tid  = threadIdx.x;
    const int path = blockIdx.y;
    const int node0 = blockIdx.x * TM;
    const int valid = min(TM, nNodes - node0);

    // ---- Edge dtype detection (block (0,0) only; block-uniform branch) ----
    if (blockIdx.x == 0 && path == 0) {
        int nz = 0;
        for (int i = tid; i < 2048; i += NODE_THREADS) nz |= edges_words[2 * i + 1];
        int any = __syncthreads_or(nz);
        if (tid == 0) g_edges_are_i64 = (any == 0) ? 1 : 0;
    }

    const float* W   = (path == 0) ? W_nb : W_self;
    const float* bW  = (path == 0) ? b_nb : b_self;
    const float* WaG = W_att1 + (size_t)path * H1 * H2;   // rows [path*128, +128) of [256][64]
    float* Aout = (path == 0) ? g_A1 : g_A2;

    // ---- Stage F tile (zero-pad invalid rows) ----
    #pragma unroll
    for (int idx = tid; idx < TM * (D_FEAT / 4); idx += NODE_THREADS) {
        int row = idx >> 5;
        int c4  = idx & 31;
        float4 v = make_float4(0.f, 0.f, 0.f, 0.f);
        if (row < valid)
            v = *reinterpret_cast<const float4*>(&features[(size_t)(node0 + row) * D_FEAT + c4 * 4]);
        *reinterpret_cast<float4*>(&FH[row * SF + c4 * 4]) = v;
    }
    __syncthreads();

    const int lane = tid & 31;
    const int wid  = tid >> 5;
    const int gid  = lane >> 2;        // 0..7
    const int tig  = lane & 3;         // 0..3
    const int wm   = wid >> 2;         // 0..1
    const int wn   = wid & 3;          // 0..3

    // ================= Phase 1 (tensor): H = relu(F @ W + b) =================
    float acc[4][4][4];
    #pragma unroll
    for (int mf = 0; mf < 4; mf++)
        #pragma unroll
        for (int nf = 0; nf < 4; nf++)
            #pragma unroll
            for (int r = 0; r < 4; r++) acc[mf][nf][r] = 0.f;

    for (int kb = 0; kb < D_FEAT / 8; kb++) {
        const int k0 = kb * 8;
        uint32_t ahi[4][4], alo[4][4];
        #pragma unroll
        for (int mf = 0; mf < 4; mf++) {
            const float* fp = &FH[(wm * 64 + mf * 16 + gid) * SF + k0 + tig];
            split_tf32(fp[0],          ahi[mf][0], alo[mf][0]);
            split_tf32(fp[8 * SF],     ahi[mf][1], alo[mf][1]);
            split_tf32(fp[4],          ahi[mf][2], alo[mf][2]);
            split_tf32(fp[8 * SF + 4], ahi[mf][3], alo[mf][3]);
        }
        uint32_t bhi[4][2], blo[4][2];
        #pragma unroll
        for (int nf = 0; nf < 4; nf++) {
            // B[n][k] = W[k][n], loaded straight from gmem (L1-resident, 64 KB)
            const int n = wn * 32 + nf * 8 + gid;
            split_tf32(__ldg(&W[(size_t)(k0 + tig) * H1 + n]),     bhi[nf][0], blo[nf][0]);
            split_tf32(__ldg(&W[(size_t)(k0 + tig + 4) * H1 + n]), bhi[nf][1], blo[nf][1]);
        }
        #pragma unroll
        for (int mf = 0; mf < 4; mf++)
            #pragma unroll
            for (int nf = 0; nf < 4; nf++) {
                mma_tf32(acc[mf][nf], ahi[mf], bhi[nf]);
                mma_tf32(acc[mf][nf], ahi[mf], blo[nf]);
                mma_tf32(acc[mf][nf], alo[mf], bhi[nf]);
            }
    }

    // bias + relu, write H back into FH (barrier: all F reads must finish first)
    float bias0[4], bias1[4];
    #pragma unroll
    for (int nf = 0; nf < 4; nf++) {
        int c = wn * 32 + nf * 8 + 2 * tig;
        bias0[nf] = __ldg(&bW[c]);
        bias1[nf] = __ldg(&bW[c + 1]);
    }
    __syncthreads();

    #pragma unroll
    for (int mf = 0; mf < 4; mf++) {
        int r0 = wm * 64 + mf * 16 + gid;
        #pragma unroll
        for (int nf = 0; nf < 4; nf++) {
            int c = wn * 32 + nf * 8 + 2 * tig;
            float2 v0, v1;
            v0.x = fmaxf(acc[mf][nf][0] + bias0[nf], 0.f);
            v0.y = fmaxf(acc[mf][nf][1] + bias1[nf], 0.f);
            v1.x = fmaxf(acc[mf][nf][2] + bias0[nf], 0.f);
            v1.y = fmaxf(acc[mf][nf][3] + bias1[nf], 0.f);
            *reinterpret_cast<float2*>(&FH[r0 * SF + c])       = v0;
            *reinterpret_cast<float2*>(&FH[(r0 + 8) * SF + c]) = v1;
        }
    }
    __syncthreads();

    // ========== Phase 2 (fma pipe, exact fp32): A = H @ Wa (+ b_att1) ==========
    const int ty = tid >> 4;           // 0..15 -> 8 rows each
    const int tx = tid & 15;           // 0..15 -> cols tx*4..tx*4+3
    float c2[8][4];
    #pragma unroll
    for (int i = 0; i < 8; i++)
        #pragma unroll
        for (int j = 0; j < 4; j++) c2[i][j] = 0.f;

    #pragma unroll 4
    for (int k = 0; k < H1; k++) {
        float a[8];
        #pragma unroll
        for (int i = 0; i < 8; i++) a[i] = FH[(ty * 8 + i) * SF + k];
        float b[4];
        #pragma unroll
        for (int j = 0; j < 4; j++) b[j] = __ldg(&WaG[(size_t)k * H2 + tx * 4 + j]);
        #pragma unroll
        for (int i = 0; i < 8; i++)
            #pragma unroll
            for (int j = 0; j < 4; j++)
                c2[i][j] = fmaf(a[i], b[j], c2[i][j]);
    }

    float ba[4] = {0.f, 0.f, 0.f, 0.f};
    if (path == 0) {
        #pragma unroll
        for (int j = 0; j < 4; j++) ba[j] = __ldg(&b_att1[tx * 4 + j]);
    }

    #pragma unroll
    for (int i = 0; i < 8; i++) {
        int m = ty * 8 + i;
        if (m < valid) {
            float4 v;
            v.x = c2[i][0] + ba[0];
            v.y = c2[i][1] + ba[1];
            v.z = c2[i][2] + ba[2];
            v.w = c2[i][3] + ba[3];
            *reinterpret_cast<float4*>(&Aout[(size_t)(node0 + m) * H2 + tx * 4]) = v;
        }
    }
}

// ---------------- Edge kernel ----------------
// 4 edges per warp, 8 lanes per edge, float4 gathers.
// out[e] = relu(A1[n1] + A2[n2]) . W_att2 + b_att2
extern "C" __global__ void __launch_bounds__(256)
edge_kernel(const void* __restrict__ edges_raw,
            const float* __restrict__ W_att2,
            const float* __restrict__ b_att2,
            float* __restrict__ out,
            int nEdges)
{
    const int warp = (blockIdx.x * blockDim.x + threadIdx.x) >> 5;
    const int lane = threadIdx.x & 31;
    const int sub  = lane >> 3;        // edge slot within warp (0..3)
    const int c    = lane & 7;         // 8-float chunk within edge (0..7)

    const long long e = (long long)warp * 4 + sub;
    if (e >= nEdges) return;           // group-uniform exit

    int n1, n2;
    if (g_edges_are_i64) {
        const longlong2 ed =
            *reinterpret_cast<const longlong2*>((const char*)edges_raw + 16 * e);
        n1 = (int)ed.x;
        n2 = (int)ed.y;
    } else {
        const int2 ed =
            *reinterpret_cast<const int2*>((const char*)edges_raw + 8 * e);
        n1 = ed.x;
        n2 = ed.y;
    }

    const float4* pa = reinterpret_cast<const float4*>(&g_A1[(size_t)n1 * H2 + c * 8]);
    const float4* pb = reinterpret_cast<const float4*>(&g_A2[(size_t)n2 * H2 + c * 8]);
    const float4 a0 = pa[0], a1 = pa[1];
    const float4 b0 = pb[0], b1 = pb[1];
    const float4 w0 = __ldg(reinterpret_cast<const float4*>(&W_att2[c * 8]));
    const float4 w1 = __ldg(reinterpret_cast<const float4*>(&W_att2[c * 8 + 4]));

    float s;
    s  = fmaxf(a0.x + b0.x, 0.f) * w0.x;
    s  = fmaf(fmaxf(a0.y + b0.y, 0.f), w0.y, s);
    s  = fmaf(fmaxf(a0.z + b0.z, 0.f), w0.z, s);
    s  = fmaf(fmaxf(a0.w + b0.w, 0.f), w0.w, s);
    s  = fmaf(fmaxf(a1.x + b1.x, 0.f), w1.x, s);
    s  = fmaf(fmaxf(a1.y + b1.y, 0.f), w1.y, s);
    s  = fmaf(fmaxf(a1.z + b1.z, 0.f), w1.z, s);
    s  = fmaf(fmaxf(a1.w + b1.w, 0.f), w1.w, s);

    const unsigned gmask = 0xFFu << (sub * 8);
    s += __shfl_xor_sync(gmask, s, 1);
    s += __shfl_xor_sync(gmask, s, 2);
    s += __shfl_xor_sync(gmask, s, 4);

    if (c == 0) out[e] = s + __ldg(&b_att2[0]);
}

// ---------------- Launch ----------------
extern "C" void kernel_launch(void* const* d_in, const int* in_sizes, int n_in,
                              void* d_out, int out_size)
{
    const float* features = (const float*)d_in[0];
    const void*  edges    = d_in[1];
    const float* W_nb     = (const float*)d_in[2];
    const float* b_nb     = (const float*)d_in[3];
    const float* W_self   = (const float*)d_in[4];
    const float* b_self   = (const float*)d_in[5];
    const float* W_att1   = (const float*)d_in[6];
    const float* b_att1   = (const float*)d_in[7];
    const float* W_att2   = (const float*)d_in[8];
    const float* b_att2   = (const float*)d_in[9];
    float* out = (float*)d_out;

    const int nNodes = in_sizes[0] / D_FEAT;
    const int nEdges = in_sizes[1] / 2;

    cudaFuncSetAttribute(node_precompute_kernel,
                         cudaFuncAttributeMaxDynamicSharedMemorySize, NODE_SMEM_BYTES);

    dim3 gridN((nNodes + TM - 1) / TM, 2);
    node_precompute_kernel<<<gridN, NODE_THREADS, NODE_SMEM_BYTES>>>(
        features, (const int*)edges, W_nb, b_nb, W_self, b_self, W_att1, b_att1, nNodes);

    const int edgesPerBlock = (256 / 32) * 4;   // 8 warps x 4 edges
    int gridE = (nEdges + edgesPerBlock - 1) / edgesPerBlock;
    edge_kernel<<<gridE, 256>>>(edges, W_att2, b_att2, out, nEdges);
}

// round 16
// speedup vs baseline: 1.3888x; 1.3888x over previous
#include <cuda_runtime.h>
#include <cstdint>

#define N_NODES_MAX 50000
#define D_FEAT 128
#define H1 128
#define H2 64

// Scratch: per-node precomputed attention contributions (bias folded into A1).
__device__ float g_A1[N_NODES_MAX * H2];
__device__ float g_A2[N_NODES_MAX * H2];
__device__ int   g_edges_are_i64;   // 1 if edge buffer is int64, 0 if int32

// ---------------- smem layout ----------------
#define TM 128
#define SF 132           // padded row stride for F/H tile (floats)
#define SW 132           // padded row stride for W tile
#define SA 68            // padded row stride for Wa tile
#define NODE_SMEM_BYTES ((TM * SF + D_FEAT * SW + H1 * SA) * 4)
#define NODE_THREADS 256

// 2xTF32 helpers -------------------------------------------------------------
// B operand fully corrected: b = bhi + blo (blo = exact fp32 remainder, then
// tf32-truncated by HW -> residual ~2^-22). A operand: hi only (truncation
// ~2^-11 |a|, uncorrected -> ~1.5e-4 relative after K=128 accumulation).
// Products: ahi*bhi + ahi*blo.
__device__ __forceinline__ uint32_t tf32_hi(float x) {
    return __float_as_uint(x) & 0xFFFFE000u;
}
__device__ __forceinline__ void split_tf32(float x, uint32_t& hi, uint32_t& lo) {
    uint32_t xb = __float_as_uint(x);
    hi = xb & 0xFFFFE000u;
    lo = __float_as_uint(x - __uint_as_float(hi));
}

__device__ __forceinline__ void mma_tf32(float* d, const uint32_t* a, const uint32_t* b) {
    asm volatile(
        "mma.sync.aligned.m16n8k8.row.col.f32.tf32.tf32.f32 "
        "{%0,%1,%2,%3}, {%4,%5,%6,%7}, {%8,%9}, {%0,%1,%2,%3};\n"
        : "+f"(d[0]), "+f"(d[1]), "+f"(d[2]), "+f"(d[3])
        : "r"(a[0]), "r"(a[1]), "r"(a[2]), "r"(a[3]), "r"(b[0]), "r"(b[1]));
}

// ---------------- Node precompute kernel (tensor-core, 2xTF32) ----------------
// gridDim.x = ceil(nNodes/128), gridDim.y = 2 (path 0 = nb/A1, path 1 = self/A2)
// 256 threads = 8 warps, warp grid 2(m) x 4(n).
// Phase 1: H[128][128] = relu(F @ W + b)       warp tile 64x32  (mf=4, nf=4)
// Phase 2: A[128][64]  = H @ Wa (+ b_att1)     warp tile 64x16  (mf=4, nf=2)
// Block (0,0) additionally detects edge dtype (int64 vs int32).
extern "C" __global__ void __launch_bounds__(NODE_THREADS, 1)
node_precompute_kernel(const float* __restrict__ features,
                       const int*   __restrict__ edges_words,
                       const float* __restrict__ W_nb,
                       const float* __restrict__ b_nb,
                       const float* __restrict__ W_self,
                       const float* __restrict__ b_self,
                       const float* __restrict__ W_att1,
                       const float* __restrict__ b_att1,
                       int nNodes)
{
    extern __shared__ float smem[];
    float* FH = smem;                                  // [TM][SF] (F, later H)
    float* Ws = smem + TM * SF;                        // [D_FEAT][SW]
    float* Wa = smem + TM * SF + D_FEAT * SW;          // [H1][SA]

    const int tid  = threadIdx.x;
    const int path = blockIdx.y;
    const int node0 = blockIdx.x * TM;
    const int valid = min(TM, nNodes - node0);

    // ---- Edge dtype detection (block (0,0) only; block-uniform branch) ----
    if (blockIdx.x == 0 && path == 0) {
        int nz = 0;
        for (int i = tid; i < 2048; i += NODE_THREADS) nz |= edges_words[2 * i + 1];
        int any = __syncthreads_or(nz);
        if (tid == 0) g_edges_are_i64 = (any == 0) ? 1 : 0;
    }

    const float* W   = (path == 0) ? W_nb : W_self;
    const float* bW  = (path == 0) ? b_nb : b_self;
    const float* WaG = W_att1 + (size_t)path * H1 * H2;   // rows [path*128, +128) of [256][64]
    float* Aout = (path == 0) ? g_A1 : g_A2;

    // ---- Stage F tile (zero-pad invalid rows) ----
    #pragma unroll
    for (int idx = tid; idx < TM * (D_FEAT / 4); idx += NODE_THREADS) {
        int row = idx >> 5;
        int c4  = idx & 31;
        float4 v = make_float4(0.f, 0.f, 0.f, 0.f);
        if (row < valid)
            v = *reinterpret_cast<const float4*>(&features[(size_t)(node0 + row) * D_FEAT + c4 * 4]);
        *reinterpret_cast<float4*>(&FH[row * SF + c4 * 4]) = v;
    }
    // ---- Stage W ----
    #pragma unroll
    for (int idx = tid; idx < D_FEAT * (H1 / 4); idx += NODE_THREADS) {
        int row = idx >> 5;
        int c4  = idx & 31;
        float4 v = *reinterpret_cast<const float4*>(&W[(size_t)row * H1 + c4 * 4]);
        *reinterpret_cast<float4*>(&Ws[row * SW + c4 * 4]) = v;
    }
    // ---- Stage Wa ----
    #pragma unroll
    for (int idx = tid; idx < H1 * (H2 / 4); idx += NODE_THREADS) {
        int row = idx >> 4;
        int c4  = idx & 15;
        float4 v = *reinterpret_cast<const float4*>(&WaG[(size_t)row * H2 + c4 * 4]);
        *reinterpret_cast<float4*>(&Wa[row * SA + c4 * 4]) = v;
    }
    __syncthreads();

    const int lane = tid & 31;
    const int wid  = tid >> 5;
    const int gid  = lane >> 2;        // group id 0..7
    const int tig  = lane & 3;         // thread-in-group 0..3
    const int wm   = wid >> 2;         // 0..1
    const int wn   = wid & 3;          // 0..3

    // ================= Phase 1: H = relu(F @ W + b) =================
    float acc[4][4][4];
    #pragma unroll
    for (int mf = 0; mf < 4; mf++)
        #pragma unroll
        for (int nf = 0; nf < 4; nf++)
            #pragma unroll
            for (int r = 0; r < 4; r++) acc[mf][nf][r] = 0.f;

    for (int kb = 0; kb < D_FEAT / 8; kb++) {
        const int k0 = kb * 8;
        uint32_t ahi[4][4];
        #pragma unroll
        for (int mf = 0; mf < 4; mf++) {
            const float* fp = &FH[(wm * 64 + mf * 16 + gid) * SF + k0 + tig];
            ahi[mf][0] = tf32_hi(fp[0]);
            ahi[mf][1] = tf32_hi(fp[8 * SF]);
            ahi[mf][2] = tf32_hi(fp[4]);
            ahi[mf][3] = tf32_hi(fp[8 * SF + 4]);
        }
        uint32_t bhi[4][2], blo[4][2];
        #pragma unroll
        for (int nf = 0; nf < 4; nf++) {
            const float* wp = &Ws[(k0 + tig) * SW + wn * 32 + nf * 8 + gid];
            split_tf32(wp[0],      bhi[nf][0], blo[nf][0]);
            split_tf32(wp[4 * SW], bhi[nf][1], blo[nf][1]);
        }
        #pragma unroll
        for (int mf = 0; mf < 4; mf++)
            #pragma unroll
            for (int nf = 0; nf < 4; nf++) {
                mma_tf32(acc[mf][nf], ahi[mf], bhi[nf]);
                mma_tf32(acc[mf][nf], ahi[mf], blo[nf]);
            }
    }

    // bias + relu, write H back into FH (all F reads done after barrier)
    float bias0[4], bias1[4];
    #pragma unroll
    for (int nf = 0; nf < 4; nf++) {
        int c = wn * 32 + nf * 8 + 2 * tig;
        bias0[nf] = __ldg(&bW[c]);
        bias1[nf] = __ldg(&bW[c + 1]);
    }
    __syncthreads();

    #pragma unroll
    for (int mf = 0; mf < 4; mf++) {
        int r0 = wm * 64 + mf * 16 + gid;
        #pragma unroll
        for (int nf = 0; nf < 4; nf++) {
            int c = wn * 32 + nf * 8 + 2 * tig;
            float2 v0, v1;
            v0.x = fmaxf(acc[mf][nf][0] + bias0[nf], 0.f);
            v0.y = fmaxf(acc[mf][nf][1] + bias1[nf], 0.f);
            v1.x = fmaxf(acc[mf][nf][2] + bias0[nf], 0.f);
            v1.y = fmaxf(acc[mf][nf][3] + bias1[nf], 0.f);
            *reinterpret_cast<float2*>(&FH[r0 * SF + c])       = v0;
            *reinterpret_cast<float2*>(&FH[(r0 + 8) * SF + c]) = v1;
        }
    }
    __syncthreads();

    // ================= Phase 2: A = H @ Wa (+ b_att1 path 0) =================
    float acc2[4][2][4];
    #pragma unroll
    for (int mf = 0; mf < 4; mf++)
        #pragma unroll
        for (int nf = 0; nf < 2; nf++)
            #pragma unroll
            for (int r = 0; r < 4; r++) acc2[mf][nf][r] = 0.f;

    for (int kb = 0; kb < H1 / 8; kb++) {
        const int k0 = kb * 8;
        uint32_t ahi[4][4];
        #pragma unroll
        for (int mf = 0; mf < 4; mf++) {
            const float* fp = &FH[(wm * 64 + mf * 16 + gid) * SF + k0 + tig];
            ahi[mf][0] = tf32_hi(fp[0]);
            ahi[mf][1] = tf32_hi(fp[8 * SF]);
            ahi[mf][2] = tf32_hi(fp[4]);
            ahi[mf][3] = tf32_hi(fp[8 * SF + 4]);
        }
        uint32_t bhi[2][2], blo[2][2];
        #pragma unroll
        for (int nf = 0; nf < 2; nf++) {
            const float* wp = &Wa[(k0 + tig) * SA + wn * 16 + nf * 8 + gid];
            split_tf32(wp[0],      bhi[nf][0], blo[nf][0]);
            split_tf32(wp[4 * SA], bhi[nf][1], blo[nf][1]);
        }
        #pragma unroll
        for (int mf = 0; mf < 4; mf++)
            #pragma unroll
            for (int nf = 0; nf < 2; nf++) {
                mma_tf32(acc2[mf][nf], ahi[mf], bhi[nf]);
                mma_tf32(acc2[mf][nf], ahi[mf], blo[nf]);
            }
    }

    float ba0[2] = {0.f, 0.f}, ba1[2] = {0.f, 0.f};
    if (path == 0) {
        #pragma unroll
        for (int nf = 0; nf < 2; nf++) {
            int c = wn * 16 + nf * 8 + 2 * tig;
            ba0[nf] = __ldg(&b_att1[c]);
            ba1[nf] = __ldg(&b_att1[c + 1]);
        }
    }

    #pragma unroll
    for (int mf = 0; mf < 4; mf++) {
        int r0 = wm * 64 + mf * 16 + gid;
        #pragma unroll
        for (int nf = 0; nf < 2; nf++) {
            int c = wn * 16 + nf * 8 + 2 * tig;
            if (r0 < valid) {
                float2 v;
                v.x = acc2[mf][nf][0] + ba0[nf];
                v.y = acc2[mf][nf][1] + ba1[nf];
                *reinterpret_cast<float2*>(&Aout[(size_t)(node0 + r0) * H2 + c]) = v;
            }
            if (r0 + 8 < valid) {
                float2 v;
                v.x = acc2[mf][nf][2] + ba0[nf];
                v.y = acc2[mf][nf][3] + ba1[nf];
                *reinterpret_cast<float2*>(&Aout[(size_t)(node0 + r0 + 8) * H2 + c]) = v;
            }
        }
    }
}

// ---------------- Edge kernel ----------------
// 4 edges per warp, 8 lanes per edge, float4 gathers.
// out[e] = relu(A1[n1] + A2[n2]) . W_att2 + b_att2
extern "C" __global__ void __launch_bounds__(256)
edge_kernel(const void* __restrict__ edges_raw,
            const float* __restrict__ W_att2,
            const float* __restrict__ b_att2,
            float* __restrict__ out,
            int nEdges)
{
    const int warp = (blockIdx.x * blockDim.x + threadIdx.x) >> 5;
    const int lane = threadIdx.x & 31;
    const int sub  = lane >> 3;        // edge slot within warp (0..3)
    const int c    = lane & 7;         // 8-float chunk within edge (0..7)

    const long long e = (long long)warp * 4 + sub;
    if (e >= nEdges) return;           // group-uniform exit

    int n1, n2;
    if (g_edges_are_i64) {
        const longlong2 ed =
            *reinterpret_cast<const longlong2*>((const char*)edges_raw + 16 * e);
        n1 = (int)ed.x;
        n2 = (int)ed.y;
    } else {
        const int2 ed =
            *reinterpret_cast<const int2*>((const char*)edges_raw + 8 * e);
        n1 = ed.x;
        n2 = ed.y;
    }

    const float4* pa = reinterpret_cast<const float4*>(&g_A1[(size_t)n1 * H2 + c * 8]);
    const float4* pb = reinterpret_cast<const float4*>(&g_A2[(size_t)n2 * H2 + c * 8]);
    const float4 a0 = pa[0], a1 = pa[1];
    const float4 b0 = pb[0], b1 = pb[1];
    const float4 w0 = __ldg(reinterpret_cast<const float4*>(&W_att2[c * 8]));
    const float4 w1 = __ldg(reinterpret_cast<const float4*>(&W_att2[c * 8 + 4]));

    float s;
    s  = fmaxf(a0.x + b0.x, 0.f) * w0.x;
    s  = fmaf(fmaxf(a0.y + b0.y, 0.f), w0.y, s);
    s  = fmaf(fmaxf(a0.z + b0.z, 0.f), w0.z, s);
    s  = fmaf(fmaxf(a0.w + b0.w, 0.f), w0.w, s);
    s  = fmaf(fmaxf(a1.x + b1.x, 0.f), w1.x, s);
    s  = fmaf(fmaxf(a1.y + b1.y, 0.f), w1.y, s);
    s  = fmaf(fmaxf(a1.z + b1.z, 0.f), w1.z, s);
    s  = fmaf(fmaxf(a1.w + b1.w, 0.f), w1.w, s);

    const unsigned gmask = 0xFFu << (sub * 8);
    s += __shfl_xor_sync(gmask, s, 1);
    s += __shfl_xor_sync(gmask, s, 2);
    s += __shfl_xor_sync(gmask, s, 4);

    if (c == 0) out[e] = s + __ldg(&b_att2[0]);
}

// ---------------- Launch ----------------
extern "C" void kernel_launch(void* const* d_in, const int* in_sizes, int n_in,
                              void* d_out, int out_size)
{
    const float* features = (const float*)d_in[0];
    const void*  edges    = d_in[1];
    const float* W_nb     = (const float*)d_in[2];
    const float* b_nb     = (const float*)d_in[3];
    const float* W_self   = (const float*)d_in[4];
    const float* b_self   = (const float*)d_in[5];
    const float* W_att1   = (const float*)d_in[6];
    const float* b_att1   = (const float*)d_in[7];
    const float* W_att2   = (const float*)d_in[8];
    const float* b_att2   = (const float*)d_in[9];
    float* out = (float*)d_out;

    const int nNodes = in_sizes[0] / D_FEAT;
    const int nEdges = in_sizes[1] / 2;

    cudaFuncSetAttribute(node_precompute_kernel,
                         cudaFuncAttributeMaxDynamicSharedMemorySize, NODE_SMEM_BYTES);

    dim3 gridN((nNodes + TM - 1) / TM, 2);
    node_precompute_kernel<<<gridN, NODE_THREADS, NODE_SMEM_BYTES>>>(
        features, (const int*)edges, W_nb, b_nb, W_self, b_self, W_att1, b_att1, nNodes);

    const int edgesPerBlock = (256 / 32) * 4;   // 8 warps x 4 edges
    int gridE = (nEdges + edgesPerBlock - 1) / edgesPerBlock;
    edge_kernel<<<gridE, 256>>>(edges, W_att2, b_att2, out, nEdges);
}

// round 17
// speedup vs baseline: 1.3892x; 1.0003x over previous
#include <cuda_runtime.h>
#include <cuda_fp16.h>
#include <cstdint>

#define N_NODES_MAX 50000
#define D_FEAT 128
#define H1 128
#define H2 64

// Scratch: per-node precomputed attention contributions, fp16 (bias folded in).
__device__ __half g_A1h[N_NODES_MAX * H2];
__device__ __half g_A2h[N_NODES_MAX * H2];
__device__ int    g_edges_are_i64;   // 1 if edge buffer is int64, 0 if int32

// ---------------- smem layout ----------------
#define TM 128
#define SF 132           // padded row stride for F/H tile (floats)
#define SW 132           // padded row stride for W tile
#define SA 68            // padded row stride for Wa tile
#define NODE_SMEM_BYTES ((TM * SF + D_FEAT * SW + H1 * SA) * 4)
#define NODE_THREADS 256

// 2xTF32 helpers -------------------------------------------------------------
// A operand: round-to-nearest tf32 (unbiased, err <= 2^-11), no correction term.
// B operand: fully corrected: bhi = RN(b), blo = b - bhi (exact; HW-truncation of
// blo contributes ~2^-21). Products: ahi*bhi + ahi*blo.
__device__ __forceinline__ uint32_t tf32_rn(float x) {
    uint32_t r;
    asm("cvt.rna.tf32.f32 %0, %1;\n" : "=r"(r) : "f"(x));
    return r;
}
__device__ __forceinline__ void split_tf32(float x, uint32_t& hi, uint32_t& lo) {
    hi = tf32_rn(x);
    lo = __float_as_uint(x - __uint_as_float(hi));
}

__device__ __forceinline__ void mma_tf32(float* d, const uint32_t* a, const uint32_t* b) {
    asm volatile(
        "mma.sync.aligned.m16n8k8.row.col.f32.tf32.tf32.f32 "
        "{%0,%1,%2,%3}, {%4,%5,%6,%7}, {%8,%9}, {%0,%1,%2,%3};\n"
        : "+f"(d[0]), "+f"(d[1]), "+f"(d[2]), "+f"(d[3])
        : "r"(a[0]), "r"(a[1]), "r"(a[2]), "r"(a[3]), "r"(b[0]), "r"(b[1]));
}

// ---------------- Node precompute kernel (tensor-core, 2xTF32-RN) ----------------
// gridDim.x = ceil(nNodes/128), gridDim.y = 2 (path 0 = nb/A1, path 1 = self/A2)
// 256 threads = 8 warps, warp grid 2(m) x 4(n).
// Phase 1: H[128][128] = relu(F @ W + b)       warp tile 64x32  (mf=4, nf=4)
// Phase 2: A[128][64]  = H @ Wa (+ b_att1)     warp tile 64x16  (mf=4, nf=2)
// A-table output stored as fp16 (halves edge-kernel gather traffic).
extern "C" __global__ void __launch_bounds__(NODE_THREADS, 1)
node_precompute_kernel(const float* __restrict__ features,
                       const int*   __restrict__ edges_words,
                       const float* __restrict__ W_nb,
                       const float* __restrict__ b_nb,
                       const float* __restrict__ W_self,
                       const float* __restrict__ b_self,
                       const float* __restrict__ W_att1,
                       const float* __restrict__ b_att1,
                       int nNodes)
{
    extern __shared__ float smem[];
    float* FH = smem;                                  // [TM][SF] (F, later H)
    float* Ws = smem + TM * SF;                        // [D_FEAT][SW]
    float* Wa = smem + TM * SF + D_FEAT * SW;          // [H1][SA]

    const int tid  = threadIdx.x;
    const int path = blockIdx.y;
    const int node0 = blockIdx.x * TM;
    const int valid = min(TM, nNodes - node0);

    // ---- Edge dtype detection (block (0,0) only; block-uniform branch) ----
    if (blockIdx.x == 0 && path == 0) {
        int nz = 0;
        for (int i = tid; i < 2048; i += NODE_THREADS) nz |= edges_words[2 * i + 1];
        int any = __syncthreads_or(nz);
        if (tid == 0) g_edges_are_i64 = (any == 0) ? 1 : 0;
    }

    const float* W   = (path == 0) ? W_nb : W_self;
    const float* bW  = (path == 0) ? b_nb : b_self;
    const float* WaG = W_att1 + (size_t)path * H1 * H2;   // rows [path*128, +128) of [256][64]
    __half* Aout = (path == 0) ? g_A1h : g_A2h;

    // ---- Stage F tile (zero-pad invalid rows) ----
    #pragma unroll
    for (int idx = tid; idx < TM * (D_FEAT / 4); idx += NODE_THREADS) {
        int row = idx >> 5;
        int c4  = idx & 31;
        float4 v = make_float4(0.f, 0.f, 0.f, 0.f);
        if (row < valid)
            v = *reinterpret_cast<const float4*>(&features[(size_t)(node0 + row) * D_FEAT + c4 * 4]);
        *reinterpret_cast<float4*>(&FH[row * SF + c4 * 4]) = v;
    }
    // ---- Stage W ----
    #pragma unroll
    for (int idx = tid; idx < D_FEAT * (H1 / 4); idx += NODE_THREADS) {
        int row = idx >> 5;
        int c4  = idx & 31;
        float4 v = *reinterpret_cast<const float4*>(&W[(size_t)row * H1 + c4 * 4]);
        *reinterpret_cast<float4*>(&Ws[row * SW + c4 * 4]) = v;
    }
    // ---- Stage Wa ----
    #pragma unroll
    for (int idx = tid; idx < H1 * (H2 / 4); idx += NODE_THREADS) {
        int row = idx >> 4;
        int c4  = idx & 15;
        float4 v = *reinterpret_cast<const float4*>(&WaG[(size_t)row * H2 + c4 * 4]);
        *reinterpret_cast<float4*>(&Wa[row * SA + c4 * 4]) = v;
    }
    __syncthreads();

    const int lane = tid & 31;
    const int wid  = tid >> 5;
    const int gid  = lane >> 2;        // group id 0..7
    const int tig  = lane & 3;         // thread-in-group 0..3
    const int wm   = wid >> 2;         // 0..1
    const int wn   = wid & 3;          // 0..3

    // ================= Phase 1: H = relu(F @ W + b) =================
    float acc[4][4][4];
    #pragma unroll
    for (int mf = 0; mf < 4; mf++)
        #pragma unroll
        for (int nf = 0; nf < 4; nf++)
            #pragma unroll
            for (int r = 0; r < 4; r++) acc[mf][nf][r] = 0.f;

    for (int kb = 0; kb < D_FEAT / 8; kb++) {
        const int k0 = kb * 8;
        uint32_t ahi[4][4];
        #pragma unroll
        for (int mf = 0; mf < 4; mf++) {
            const float* fp = &FH[(wm * 64 + mf * 16 + gid) * SF + k0 + tig];
            ahi[mf][0] = tf32_rn(fp[0]);
            ahi[mf][1] = tf32_rn(fp[8 * SF]);
            ahi[mf][2] = tf32_rn(fp[4]);
            ahi[mf][3] = tf32_rn(fp[8 * SF + 4]);
        }
        uint32_t bhi[4][2], blo[4][2];
        #pragma unroll
        for (int nf = 0; nf < 4; nf++) {
            const float* wp = &Ws[(k0 + tig) * SW + wn * 32 + nf * 8 + gid];
            split_tf32(wp[0],      bhi[nf][0], blo[nf][0]);
            split_tf32(wp[4 * SW], bhi[nf][1], blo[nf][1]);
        }
        #pragma unroll
        for (int mf = 0; mf < 4; mf++)
            #pragma unroll
            for (int nf = 0; nf < 4; nf++) {
                mma_tf32(acc[mf][nf], ahi[mf], bhi[nf]);
                mma_tf32(acc[mf][nf], ahi[mf], blo[nf]);
            }
    }

    // bias + relu, write H back into FH (all F reads done after barrier)
    float bias0[4], bias1[4];
    #pragma unroll
    for (int nf = 0; nf < 4; nf++) {
        int c = wn * 32 + nf * 8 + 2 * tig;
        bias0[nf] = __ldg(&bW[c]);
        bias1[nf] = __ldg(&bW[c + 1]);
    }
    __syncthreads();

    #pragma unroll
    for (int mf = 0; mf < 4; mf++) {
        int r0 = wm * 64 + mf * 16 + gid;
        #pragma unroll
        for (int nf = 0; nf < 4; nf++) {
            int c = wn * 32 + nf * 8 + 2 * tig;
            float2 v0, v1;
            v0.x = fmaxf(acc[mf][nf][0] + bias0[nf], 0.f);
            v0.y = fmaxf(acc[mf][nf][1] + bias1[nf], 0.f);
            v1.x = fmaxf(acc[mf][nf][2] + bias0[nf], 0.f);
            v1.y = fmaxf(acc[mf][nf][3] + bias1[nf], 0.f);
            *reinterpret_cast<float2*>(&FH[r0 * SF + c])       = v0;
            *reinterpret_cast<float2*>(&FH[(r0 + 8) * SF + c]) = v1;
        }
    }
    __syncthreads();

    // ================= Phase 2: A = H @ Wa (+ b_att1 path 0) =================
    float acc2[4][2][4];
    #pragma unroll
    for (int mf = 0; mf < 4; mf++)
        #pragma unroll
        for (int nf = 0; nf < 2; nf++)
            #pragma unroll
            for (int r = 0; r < 4; r++) acc2[mf][nf][r] = 0.f;

    for (int kb = 0; kb < H1 / 8; kb++) {
        const int k0 = kb * 8;
        uint32_t ahi[4][4];
        #pragma unroll
        for (int mf = 0; mf < 4; mf++) {
            const float* fp = &FH[(wm * 64 + mf * 16 + gid) * SF + k0 + tig];
            ahi[mf][0] = tf32_rn(fp[0]);
            ahi[mf][1] = tf32_rn(fp[8 * SF]);
            ahi[mf][2] = tf32_rn(fp[4]);
            ahi[mf][3] = tf32_rn(fp[8 * SF + 4]);
        }
        uint32_t bhi[2][2], blo[2][2];
        #pragma unroll
        for (int nf = 0; nf < 2; nf++) {
            const float* wp = &Wa[(k0 + tig) * SA + wn * 16 + nf * 8 + gid];
            split_tf32(wp[0],      bhi[nf][0], blo[nf][0]);
            split_tf32(wp[4 * SA], bhi[nf][1], blo[nf][1]);
        }
        #pragma unroll
        for (int mf = 0; mf < 4; mf++)
            #pragma unroll
            for (int nf = 0; nf < 2; nf++) {
                mma_tf32(acc2[mf][nf], ahi[mf], bhi[nf]);
                mma_tf32(acc2[mf][nf], ahi[mf], blo[nf]);
            }
    }

    float ba0[2] = {0.f, 0.f}, ba1[2] = {0.f, 0.f};
    if (path == 0) {
        #pragma unroll
        for (int nf = 0; nf < 2; nf++) {
            int c = wn * 16 + nf * 8 + 2 * tig;
            ba0[nf] = __ldg(&b_att1[c]);
            ba1[nf] = __ldg(&b_att1[c + 1]);
        }
    }

    #pragma unroll
    for (int mf = 0; mf < 4; mf++) {
        int r0 = wm * 64 + mf * 16 + gid;
        #pragma unroll
        for (int nf = 0; nf < 2; nf++) {
            int c = wn * 16 + nf * 8 + 2 * tig;   // even
            if (r0 < valid) {
                __half2 h = __floats2half2_rn(acc2[mf][nf][0] + ba0[nf],
                                              acc2[mf][nf][1] + ba1[nf]);
                *reinterpret_cast<__half2*>(&Aout[(size_t)(node0 + r0) * H2 + c]) = h;
            }
            if (r0 + 8 < valid) {
                __half2 h = __floats2half2_rn(acc2[mf][nf][2] + ba0[nf],
                                              acc2[mf][nf][3] + ba1[nf]);
                *reinterpret_cast<__half2*>(&Aout[(size_t)(node0 + r0 + 8) * H2 + c]) = h;
            }
        }
    }
}

// ---------------- Edge kernel ----------------
// 4 edges per warp, 8 lanes per edge, one 16B gather per table per lane (fp16).
// out[e] = relu(A1[n1] + A2[n2]) . W_att2 + b_att2
extern "C" __global__ void __launch_bounds__(256)
edge_kernel(const void* __restrict__ edges_raw,
            const float* __restrict__ W_att2,
            const float* __restrict__ b_att2,
            float* __restrict__ out,
            int nEdges)
{
    const int warp = (blockIdx.x * blockDim.x + threadIdx.x) >> 5;
    const int lane = threadIdx.x & 31;
    const int sub  = lane >> 3;        // edge slot within warp (0..3)
    const int c    = lane & 7;         // 8-half chunk within edge (0..7)

    const long long e = (long long)warp * 4 + sub;
    if (e >= nEdges) return;           // group-uniform exit

    int n1, n2;
    if (g_edges_are_i64) {
        const longlong2 ed =
            *reinterpret_cast<const longlong2*>((const char*)edges_raw + 16 * e);
        n1 = (int)ed.x;
        n2 = (int)ed.y;
    } else {
        const int2 ed =
            *reinterpret_cast<const int2*>((const char*)edges_raw + 8 * e);
        n1 = ed.x;
        n2 = ed.y;
    }

    // 8 halves (16 B) per table per lane
    const uint4 ua = *reinterpret_cast<const uint4*>(&g_A1h[(size_t)n1 * H2 + c * 8]);
    const uint4 ub = *reinterpret_cast<const uint4*>(&g_A2h[(size_t)n2 * H2 + c * 8]);
    const float4 w0 = __ldg(reinterpret_cast<const float4*>(&W_att2[c * 8]));
    const float4 w1 = __ldg(reinterpret_cast<const float4*>(&W_att2[c * 8 + 4]));

    float2 a0 = __half22float2(*reinterpret_cast<const __half2*>(&ua.x));
    float2 a1 = __half22float2(*reinterpret_cast<const __half2*>(&ua.y));
    float2 a2 = __half22float2(*reinterpret_cast<const __half2*>(&ua.z));
    float2 a3 = __half22float2(*reinterpret_cast<const __half2*>(&ua.w));
    float2 b0 = __half22float2(*reinterpret_cast<const __half2*>(&ub.x));
    float2 b1 = __half22float2(*reinterpret_cast<const __half2*>(&ub.y));
    float2 b2 = __half22float2(*reinterpret_cast<const __half2*>(&ub.z));
    float2 b3 = __half22float2(*reinterpret_cast<const __half2*>(&ub.w));

    float s;
    s  = fmaxf(a0.x + b0.x, 0.f) * w0.x;
    s  = fmaf(fmaxf(a0.y + b0.y, 0.f), w0.y, s);
    s  = fmaf(fmaxf(a1.x + b1.x, 0.f), w0.z, s);
    s  = fmaf(fmaxf(a1.y + b1.y, 0.f), w0.w, s);
    s  = fmaf(fmaxf(a2.x + b2.x, 0.f), w1.x, s);
    s  = fmaf(fmaxf(a2.y + b2.y, 0.f), w1.y, s);
    s  = fmaf(fmaxf(a3.x + b3.x, 0.f), w1.z, s);
    s  = fmaf(fmaxf(a3.y + b3.y, 0.f), w1.w, s);

    const unsigned gmask = 0xFFu << (sub * 8);
    s += __shfl_xor_sync(gmask, s, 1);
    s += __shfl_xor_sync(gmask, s, 2);
    s += __shfl_xor_sync(gmask, s, 4);

    if (c == 0) out[e] = s + __ldg(&b_att2[0]);
}

// ---------------- Launch ----------------
extern "C" void kernel_launch(void* const* d_in, const int* in_sizes, int n_in,
                              void* d_out, int out_size)
{
    const float* features = (const float*)d_in[0];
    const void*  edges    = d_in[1];
    const float* W_nb     = (const float*)d_in[2];
    const float* b_nb     = (const float*)d_in[3];
    const float* W_self   = (const float*)d_in[4];
    const float* b_self   = (const float*)d_in[5];
    const float* W_att1   = (const float*)d_in[6];
    const float* b_att1   = (const float*)d_in[7];
    const float* W_att2   = (const float*)d_in[8];
    const float* b_att2   = (const float*)d_in[9];
    float* out = (float*)d_out;

    const int nNodes = in_sizes[0] / D_FEAT;
    const int nEdges = in_sizes[1] / 2;

    cudaFuncSetAttribute(node_precompute_kernel,
                         cudaFuncAttributeMaxDynamicSharedMemorySize, NODE_SMEM_BYTES);

    dim3 gridN((nNodes + TM - 1) / TM, 2);
    node_precompute_kernel<<<gridN, NODE_THREADS, NODE_SMEM_BYTES>>>(
        features, (const int*)edges, W_nb, b_nb, W_self, b_self, W_att1, b_att1, nNodes);

    const int edgesPerBlock = (256 / 32) * 4;   // 8 warps x 4 edges
    int gridE = (nEdges + edgesPerBlock - 1) / edgesPerBlock;
    edge_kernel<<<gridE, 256>>>(edges, W_att2, b_att2, out, nEdges);
}